// round 1
// baseline (speedup 1.0000x reference)
#include <cuda_runtime.h>
#include <math.h>

#define NN 100000
#define DD 128
#define LN_EPS 1e-5f

// Scratch (device globals — no allocation allowed)
__device__ float g_mi[(size_t)NN * DD];
__device__ float g_mo[(size_t)NN * DD];
__device__ float g_h0[(size_t)NN * DD];
__device__ float g_h1[(size_t)NN * DD];

// ---------------------------------------------------------------------------
// Zero mi and mo (atomics need clean accumulators every replay)
// ---------------------------------------------------------------------------
__global__ void zero2_kernel(float4* __restrict__ a, float4* __restrict__ b, int n4) {
    int i = blockIdx.x * blockDim.x + threadIdx.x;
    float4 z = make_float4(0.f, 0.f, 0.f, 0.f);
    if (i < n4) { a[i] = z; b[i] = z; }
}

// ---------------------------------------------------------------------------
// Edge scatter: warp per edge, lane covers 4 channels (float4).
//   mi[end]   += e * x[start]
//   mo[start] += e * x[end]
// Uses red.global.add.v4.f32 (no-return vector atomic) to quarter atomic count.
// ---------------------------------------------------------------------------
__global__ void scatter_kernel(const float* __restrict__ x,
                               const float* __restrict__ ew,
                               const int*   __restrict__ ei,
                               float* __restrict__ mi,
                               float* __restrict__ mo,
                               int E) {
    int gt   = blockIdx.x * blockDim.x + threadIdx.x;
    int wid  = gt >> 5;
    int lane = gt & 31;
    if (wid >= E) return;

    int s = 0, t = 0; float w = 0.f;
    if (lane == 0) {
        s = ei[wid];
        t = ei[E + wid];
        w = ew[wid];
    }
    s = __shfl_sync(0xffffffffu, s, 0);
    t = __shfl_sync(0xffffffffu, t, 0);
    w = __shfl_sync(0xffffffffu, w, 0);

    const float4 xs = *(const float4*)(x + (size_t)s * DD + lane * 4);
    const float4 xt = *(const float4*)(x + (size_t)t * DD + lane * 4);

    float* pmi = mi + (size_t)t * DD + lane * 4;
    float* pmo = mo + (size_t)s * DD + lane * 4;

    asm volatile("red.global.add.v4.f32 [%0], {%1,%2,%3,%4};" ::
                 "l"(pmi), "f"(xs.x * w), "f"(xs.y * w), "f"(xs.z * w), "f"(xs.w * w)
                 : "memory");
    asm volatile("red.global.add.v4.f32 [%0], {%1,%2,%3,%4};" ::
                 "l"(pmo), "f"(xt.x * w), "f"(xt.y * w), "f"(xt.z * w), "f"(xt.w * w)
                 : "memory");
}

// ---------------------------------------------------------------------------
// Fused GEMM + bias + LayerNorm + tanh.
//   out[m, 0:128] = tanh(LN(sum_mat A_mat[m, 0:128] @ W[mat] + bias))
// BM=128 rows, BN=128 cols (full H), BK=16, 256 threads, 8x8 microtile.
// Epilogue: per-row mean/var via 16-partials smem reduction; output written
// straight from registers (no C staging buffer).
// ---------------------------------------------------------------------------
__global__ __launch_bounds__(256)
void gemm_ln_tanh_kernel(const float* __restrict__ A0,
                         const float* __restrict__ A1,
                         const float* __restrict__ A2,
                         int nmat,
                         const float* __restrict__ W,      // nmat contiguous [128,128] slices
                         const float* __restrict__ bias,   // [128]
                         const float* __restrict__ gamma,  // [128]
                         const float* __restrict__ beta,   // [128]
                         float* __restrict__ out,
                         int N) {
    __shared__ float As[16][132];       // [k][m], padded stride
    __shared__ float Bs[16][128];       // [k][n]
    __shared__ float2 reds[128][16];    // per-row (sum, sumsq) partials per tx
    __shared__ float2 ms[128];          // per-row (mean, rstd)

    const int tid = threadIdx.x;
    const int tx  = tid & 15;   // column group: cols tx*8 .. tx*8+7
    const int ty  = tid >> 4;   // row group:    rows ty*8 .. ty*8+7
    const int blockM = blockIdx.x * 128;

    float acc[8][8];
#pragma unroll
    for (int i = 0; i < 8; i++)
#pragma unroll
        for (int j = 0; j < 8; j++) acc[i][j] = 0.f;

    // A loader mapping: thread -> (row, k-half)
    const int a_row = tid >> 1;          // 0..127
    const int a_kh  = (tid & 1) * 8;     // 0 or 8 (covers 8 consecutive k)
    // B loader mapping: 2 consecutive float4 per thread
    const int b_e0 = tid * 2;            // float4 element index in 16x32 grid

    for (int mat = 0; mat < nmat; ++mat) {
        const float* A  = (mat == 0) ? A0 : ((mat == 1) ? A1 : A2);
        const float* Wm = W + (size_t)mat * 128 * 128;

        for (int kt = 0; kt < 128; kt += 16) {
            // ---- load A tile (transposed into As[k][m]) ----
            {
                const int gm = blockM + a_row;
                float4 av0, av1;
                if (gm < N) {
                    const float* ap = A + (size_t)gm * 128 + kt + a_kh;
                    av0 = *(const float4*)(ap);
                    av1 = *(const float4*)(ap + 4);
                } else {
                    av0 = make_float4(0.f, 0.f, 0.f, 0.f);
                    av1 = av0;
                }
                As[a_kh + 0][a_row] = av0.x;
                As[a_kh + 1][a_row] = av0.y;
                As[a_kh + 2][a_row] = av0.z;
                As[a_kh + 3][a_row] = av0.w;
                As[a_kh + 4][a_row] = av1.x;
                As[a_kh + 5][a_row] = av1.y;
                As[a_kh + 6][a_row] = av1.z;
                As[a_kh + 7][a_row] = av1.w;
            }
            // ---- load B tile ----
            {
                int e  = b_e0;
                int k  = e >> 5, n4 = e & 31;
                *(float4*)&Bs[k][n4 * 4] =
                    *(const float4*)(Wm + (size_t)(kt + k) * 128 + n4 * 4);
                e++;
                k = e >> 5; n4 = e & 31;
                *(float4*)&Bs[k][n4 * 4] =
                    *(const float4*)(Wm + (size_t)(kt + k) * 128 + n4 * 4);
            }
            __syncthreads();

#pragma unroll
            for (int k = 0; k < 16; k++) {
                float a[8], b[8];
#pragma unroll
                for (int i = 0; i < 8; i++) a[i] = As[k][ty * 8 + i];
#pragma unroll
                for (int j = 0; j < 8; j++) b[j] = Bs[k][tx * 8 + j];
#pragma unroll
                for (int i = 0; i < 8; i++)
#pragma unroll
                    for (int j = 0; j < 8; j++) acc[i][j] += a[i] * b[j];
            }
            __syncthreads();
        }
    }

    // ---- epilogue: bias, per-row LN stats partials ----
#pragma unroll
    for (int i = 0; i < 8; i++) {
        float s = 0.f, q = 0.f;
#pragma unroll
        for (int j = 0; j < 8; j++) {
            float v = acc[i][j] + bias[tx * 8 + j];
            acc[i][j] = v;
            s += v;
            q += v * v;
        }
        reds[ty * 8 + i][tx] = make_float2(s, q);
    }
    __syncthreads();

    if (tid < 128) {
        float s = 0.f, q = 0.f;
#pragma unroll
        for (int t = 0; t < 16; t++) {
            float2 p = reds[tid][t];
            s += p.x;
            q += p.y;
        }
        float mean = s * (1.f / 128.f);
        float var  = q * (1.f / 128.f) - mean * mean;
        ms[tid] = make_float2(mean, rsqrtf(var + LN_EPS));
    }
    __syncthreads();

#pragma unroll
    for (int i = 0; i < 8; i++) {
        const int r  = ty * 8 + i;
        const int gm = blockM + r;
        if (gm >= N) continue;
        const float2 m = ms[r];
        float o[8];
#pragma unroll
        for (int j = 0; j < 8; j++) {
            const int c = tx * 8 + j;
            o[j] = tanhf((acc[i][j] - m.x) * m.y * gamma[c] + beta[c]);
        }
        float4* op = (float4*)(out + (size_t)gm * 128 + tx * 8);
        op[0] = make_float4(o[0], o[1], o[2], o[3]);
        op[1] = make_float4(o[4], o[5], o[6], o[7]);
    }
}

// ---------------------------------------------------------------------------
// Launch
// ---------------------------------------------------------------------------
extern "C" void kernel_launch(void* const* d_in, const int* in_sizes, int n_in,
                              void* d_out, int out_size) {
    const float* x   = (const float*)d_in[0];
    const float* e   = (const float*)d_in[1];
    const int*   ei  = (const int*)d_in[2];
    const float* W0  = (const float*)d_in[3];
    const float* b0  = (const float*)d_in[4];
    const float* g0  = (const float*)d_in[5];
    const float* be0 = (const float*)d_in[6];
    const float* W   = (const float*)d_in[7];
    const float* b   = (const float*)d_in[8];
    const float* g   = (const float*)d_in[9];
    const float* be  = (const float*)d_in[10];
    float* out = (float*)d_out;

    const int N = in_sizes[0] / DD;   // 100000
    const int E = in_sizes[1];        // 1600000

    float *mi, *mo, *h0, *h1;
    cudaGetSymbolAddress((void**)&mi, g_mi);
    cudaGetSymbolAddress((void**)&mo, g_mo);
    cudaGetSymbolAddress((void**)&h0, g_h0);
    cudaGetSymbolAddress((void**)&h1, g_h1);

    // 1) zero accumulators
    {
        int n4 = N * DD / 4;
        int blocks = (n4 + 255) / 256;
        zero2_kernel<<<blocks, 256>>>((float4*)mi, (float4*)mo, n4);
    }

    // 2) edge scatter (warp per edge)
    {
        long long threads = (long long)E * 32;
        int blocks = (int)((threads + 255) / 256);
        scatter_kernel<<<blocks, 256>>>(x, e, ei, mi, mo, E);
    }

    // 3) four fused GEMM+LN+tanh layers
    {
        int blocks = (N + 127) / 128;
        // layer 0: concat([mi, mo, x]) @ W0  ==  mi@W0[0:128] + mo@W0[128:256] + x@W0[256:384]
        gemm_ln_tanh_kernel<<<blocks, 256>>>(mi, mo, x, 3, W0, b0, g0, be0, h0, N);
        gemm_ln_tanh_kernel<<<blocks, 256>>>(h0, nullptr, nullptr, 1,
                                             W, b, g, be, h1, N);
        gemm_ln_tanh_kernel<<<blocks, 256>>>(h1, nullptr, nullptr, 1,
                                             W + 128 * 128, b + 128, g + 128, be + 128, h0, N);
        gemm_ln_tanh_kernel<<<blocks, 256>>>(h0, nullptr, nullptr, 1,
                                             W + 2 * 128 * 128, b + 2 * 128, g + 2 * 128, be + 2 * 128,
                                             out, N);
    }
}

// round 8
// speedup vs baseline: 1.0312x; 1.0312x over previous
#include <cuda_runtime.h>
#include <math.h>
#include <stdint.h>

#define NN 100000
#define DD 128
#define LN_EPS 1e-5f

// Scratch (device globals — no allocation allowed)
__device__ float g_mi[(size_t)NN * DD];
__device__ float g_mo[(size_t)NN * DD];
__device__ float g_h0[(size_t)NN * DD];
__device__ float g_h1[(size_t)NN * DD];

// ---------------------------------------------------------------------------
// Helpers
// ---------------------------------------------------------------------------
__device__ __forceinline__ uint32_t smem_u32(const void* p) {
    uint32_t a;
    asm("{ .reg .u64 t; cvta.to.shared.u64 t, %1; cvt.u32.u64 %0, t; }"
        : "=r"(a) : "l"(p));
    return a;
}
// 16B async copy with zero-fill when src_bytes==0 (OOB-safe: 0 bytes read)
__device__ __forceinline__ void cp_async16(uint32_t dst, const void* src, int src_bytes) {
    asm volatile("cp.async.cg.shared.global [%0], [%1], 16, %2;"
                 :: "r"(dst), "l"(src), "r"(src_bytes) : "memory");
}
#define CP_COMMIT() asm volatile("cp.async.commit_group;" ::: "memory")
#define CP_WAIT1()  asm volatile("cp.async.wait_group 1;" ::: "memory")
#define CP_WAIT0()  asm volatile("cp.async.wait_group 0;" ::: "memory")

// ---------------------------------------------------------------------------
// Zero mi and mo
// ---------------------------------------------------------------------------
__global__ void zero2_kernel(float4* __restrict__ a, float4* __restrict__ b, int n4) {
    int i = blockIdx.x * blockDim.x + threadIdx.x;
    float4 z = make_float4(0.f, 0.f, 0.f, 0.f);
    if (i < n4) { a[i] = z; b[i] = z; }
}

// ---------------------------------------------------------------------------
// Edge scatter (warp per edge, vector red.global) — LTS-bound, unchanged
// ---------------------------------------------------------------------------
__global__ void scatter_kernel(const float* __restrict__ x,
                               const float* __restrict__ ew,
                               const int*   __restrict__ ei,
                               float* __restrict__ mi,
                               float* __restrict__ mo,
                               int E) {
    int gt   = blockIdx.x * blockDim.x + threadIdx.x;
    int wid  = gt >> 5;
    int lane = gt & 31;
    if (wid >= E) return;

    int s = 0, t = 0; float w = 0.f;
    if (lane == 0) { s = ei[wid]; t = ei[E + wid]; w = ew[wid]; }
    s = __shfl_sync(0xffffffffu, s, 0);
    t = __shfl_sync(0xffffffffu, t, 0);
    w = __shfl_sync(0xffffffffu, w, 0);

    const float4 xs = *(const float4*)(x + (size_t)s * DD + lane * 4);
    const float4 xt = *(const float4*)(x + (size_t)t * DD + lane * 4);

    float* pmi = mi + (size_t)t * DD + lane * 4;
    float* pmo = mo + (size_t)s * DD + lane * 4;

    asm volatile("red.global.add.v4.f32 [%0], {%1,%2,%3,%4};" ::
                 "l"(pmi), "f"(xs.x * w), "f"(xs.y * w), "f"(xs.z * w), "f"(xs.w * w)
                 : "memory");
    asm volatile("red.global.add.v4.f32 [%0], {%1,%2,%3,%4};" ::
                 "l"(pmo), "f"(xt.x * w), "f"(xt.y * w), "f"(xt.z * w), "f"(xt.w * w)
                 : "memory");
}

// ---------------------------------------------------------------------------
// Fused GEMM + bias + LayerNorm + tanh, v2:
//   cp.async double-buffered tiles (BM=128, BN=128, BK=16), 256 thr, 8x8 micro.
//   A kept row-major in smem As[m][20] (pad 20 floats = 80B, 16B-aligned rows
//   so cp.async 16B chunks land correctly); B as Bs[k][n].
//   Inner loop steps k in pairs: 8 LDS.64 (A, broadcast) + 4 LDS.128 (B)
//   + 128 FFMA per pair.
// ---------------------------------------------------------------------------
__global__ __launch_bounds__(256, 2)
void gemm_ln_tanh_v2(const float* __restrict__ A0,
                     const float* __restrict__ A1,
                     const float* __restrict__ A2,
                     int nmat,
                     const float* __restrict__ W,      // nmat contiguous [128,128]
                     const float* __restrict__ bias,   // [128]
                     const float* __restrict__ gamma,  // [128]
                     const float* __restrict__ beta,   // [128]
                     float* __restrict__ out,
                     int N) {
    __shared__ float As[2][128][20];   // 20480 B
    __shared__ float Bs[2][16][128];   // 16384 B
    __shared__ float2 reds[128][16];   //  4096 B
    __shared__ float2 ms[128];         //  1024 B

    const int tid = threadIdx.x;
    const int tx  = tid & 15;          // col group: cols tx*8..+7
    const int ty  = tid >> 4;          // row group: rows ty*8..+7
    const int blockM = blockIdx.x * 128;

    // loader mappings
    const int a_row = tid >> 1;            // 0..127
    const int a_kh  = (tid & 1) * 8;       // k offset 0 or 8 (two 16B chunks)
    const int b_f   = tid * 2;             // two consecutive float4 of B tile
    const int b_k0  = b_f >> 5;
    const int b_n0  = (b_f & 31) * 4;
    const int b_k1  = (b_f + 1) >> 5;
    const int b_n1  = ((b_f + 1) & 31) * 4;

    const int a_ok = (blockM + a_row < N) ? 16 : 0;

    const float* mats[3] = {A0, A1, A2};
    const int T = nmat * 8;                // total BK=16 tiles

    const uint32_t as_base = smem_u32(&As[0][0][0]);
    const uint32_t bs_base = smem_u32(&Bs[0][0][0]);

    float acc[8][8];
#pragma unroll
    for (int i = 0; i < 8; i++)
#pragma unroll
        for (int j = 0; j < 8; j++) acc[i][j] = 0.f;

    // issue tile t into buffer buf
    auto load_tile = [&](int t, int buf) {
        const int mat = t >> 3;
        const int kt  = (t & 7) * 16;
        const float* A  = mats[mat];
        const float* Wm = W + (size_t)mat * 128 * 128;

        const float* asrc = A + (size_t)(blockM + a_row) * 128 + kt + a_kh;
        const uint32_t adst = as_base + (uint32_t)((buf * 128 + a_row) * 20 + a_kh) * 4u;
        cp_async16(adst, asrc, a_ok);
        cp_async16(adst + 16, asrc + 4, a_ok);

        const uint32_t bbase = bs_base + (uint32_t)(buf * 16 * 128) * 4u;
        cp_async16(bbase + (uint32_t)(b_k0 * 128 + b_n0) * 4u,
                   Wm + (size_t)(kt + b_k0) * 128 + b_n0, 16);
        cp_async16(bbase + (uint32_t)(b_k1 * 128 + b_n1) * 4u,
                   Wm + (size_t)(kt + b_k1) * 128 + b_n1, 16);
        CP_COMMIT();
    };

    load_tile(0, 0);

    for (int t = 0; t < T; ++t) {
        const int buf = t & 1;
        if (t + 1 < T) {
            load_tile(t + 1, (t + 1) & 1);
            CP_WAIT1();
        } else {
            CP_WAIT0();
        }
        __syncthreads();

#pragma unroll
        for (int kg = 0; kg < 8; ++kg) {
            const int k = kg * 2;
            float2 a2[8];
#pragma unroll
            for (int i = 0; i < 8; i++)
                a2[i] = *(const float2*)&As[buf][ty * 8 + i][k];
            const float4 bA0 = *(const float4*)&Bs[buf][k][tx * 8];
            const float4 bA1 = *(const float4*)&Bs[buf][k][tx * 8 + 4];
            const float4 bB0 = *(const float4*)&Bs[buf][k + 1][tx * 8];
            const float4 bB1 = *(const float4*)&Bs[buf][k + 1][tx * 8 + 4];
            const float bA[8] = {bA0.x, bA0.y, bA0.z, bA0.w, bA1.x, bA1.y, bA1.z, bA1.w};
            const float bB[8] = {bB0.x, bB0.y, bB0.z, bB0.w, bB1.x, bB1.y, bB1.z, bB1.w};
#pragma unroll
            for (int i = 0; i < 8; i++) {
#pragma unroll
                for (int j = 0; j < 8; j++) {
                    acc[i][j] += a2[i].x * bA[j];
                    acc[i][j] += a2[i].y * bB[j];
                }
            }
        }
        __syncthreads();
    }

    // ---- epilogue: bias, per-row LN stats partials ----
#pragma unroll
    for (int i = 0; i < 8; i++) {
        float s = 0.f, q = 0.f;
#pragma unroll
        for (int j = 0; j < 8; j++) {
            float v = acc[i][j] + bias[tx * 8 + j];
            acc[i][j] = v;
            s += v;
            q += v * v;
        }
        reds[ty * 8 + i][tx] = make_float2(s, q);
    }
    __syncthreads();

    if (tid < 128) {
        float s = 0.f, q = 0.f;
#pragma unroll
        for (int t2 = 0; t2 < 16; t2++) {
            float2 p = reds[tid][t2];
            s += p.x;
            q += p.y;
        }
        float mean = s * (1.f / 128.f);
        float var  = q * (1.f / 128.f) - mean * mean;
        ms[tid] = make_float2(mean, rsqrtf(var + LN_EPS));
    }
    __syncthreads();

#pragma unroll
    for (int i = 0; i < 8; i++) {
        const int r  = ty * 8 + i;
        const int gm = blockM + r;
        if (gm >= N) continue;
        const float2 m = ms[r];
        float o[8];
#pragma unroll
        for (int j = 0; j < 8; j++) {
            const int c = tx * 8 + j;
            o[j] = tanhf((acc[i][j] - m.x) * m.y * gamma[c] + beta[c]);
        }
        float4* op = (float4*)(out + (size_t)gm * 128 + tx * 8);
        op[0] = make_float4(o[0], o[1], o[2], o[3]);
        op[1] = make_float4(o[4], o[5], o[6], o[7]);
    }
}

// ---------------------------------------------------------------------------
// Launch
// ---------------------------------------------------------------------------
extern "C" void kernel_launch(void* const* d_in, const int* in_sizes, int n_in,
                              void* d_out, int out_size) {
    const float* x   = (const float*)d_in[0];
    const float* e   = (const float*)d_in[1];
    const int*   ei  = (const int*)d_in[2];
    const float* W0  = (const float*)d_in[3];
    const float* b0  = (const float*)d_in[4];
    const float* g0  = (const float*)d_in[5];
    const float* be0 = (const float*)d_in[6];
    const float* W   = (const float*)d_in[7];
    const float* b   = (const float*)d_in[8];
    const float* g   = (const float*)d_in[9];
    const float* be  = (const float*)d_in[10];
    float* out = (float*)d_out;

    const int N = in_sizes[0] / DD;   // 100000
    const int E = in_sizes[1];        // 1600000

    float *mi, *mo, *h0, *h1;
    cudaGetSymbolAddress((void**)&mi, g_mi);
    cudaGetSymbolAddress((void**)&mo, g_mo);
    cudaGetSymbolAddress((void**)&h0, g_h0);
    cudaGetSymbolAddress((void**)&h1, g_h1);

    // 1) zero accumulators
    {
        int n4 = N * DD / 4;
        int blocks = (n4 + 255) / 256;
        zero2_kernel<<<blocks, 256>>>((float4*)mi, (float4*)mo, n4);
    }

    // 2) edge scatter
    {
        long long threads = (long long)E * 32;
        int blocks = (int)((threads + 255) / 256);
        scatter_kernel<<<blocks, 256>>>(x, e, ei, mi, mo, E);
    }

    // 3) four fused GEMM+LN+tanh layers (cp.async double-buffered SGEMM)
    {
        int blocks = (N + 127) / 128;
        gemm_ln_tanh_v2<<<blocks, 256>>>(mi, mo, x, 3, W0, b0, g0, be0, h0, N);
        gemm_ln_tanh_v2<<<blocks, 256>>>(h0, nullptr, nullptr, 1,
                                         W, b, g, be, h1, N);
        gemm_ln_tanh_v2<<<blocks, 256>>>(h1, nullptr, nullptr, 1,
                                         W + 128 * 128, b + 128, g + 128, be + 128, h0, N);
        gemm_ln_tanh_v2<<<blocks, 256>>>(h0, nullptr, nullptr, 1,
                                         W + 2 * 128 * 128, b + 2 * 128, g + 2 * 128, be + 2 * 128,
                                         out, N);
    }
}